// round 17
// baseline (speedup 1.0000x reference)
#include <cuda_runtime.h>
#include <cuda_fp16.h>
#include <cstdint>

#define NODES 50
#define EPG   400
#define NGRAPH 512
#define NN    (NGRAPH*NODES)   // 25600
#define NE    (NGRAPH*EPG)     // 204800
#define FDIM  512
#define HEADS 8
#define CH    64
#define NA    5
#define GRUH  128
#define GRUI  1024
#define G3    384
#define EMAX  456              // padded per-graph edge capacity (450 used)

// ---------------- scratch (static device globals; no allocation) ----------------
__device__ __half g_Hh[NN*FDIM];        // node features (GAT layer input), fp16
__device__ float g_bufB[NN*FDIM];       // layer-3 output fp32 (pool/agent input)
__device__ __half g_Ah[NN*FDIM];        // GEMM A operand
__device__ __half g_Bh[GRUI*G3 > FDIM*FDIM ? GRUI*G3 : FDIM*FDIM];
__device__ float g_alpha[NGRAPH*EMAX*HEADS];
__device__ int   g_srcb[NGRAPH*EMAX];
__device__ int   g_offb[NGRAPH*51];
__device__ float g_GI[NGRAPH*NA*G3];
__device__ float g_gruout[NGRAPH*NA*GRUH];

// ---------------- helpers ----------------
__device__ __forceinline__ uint32_t smem_u32(const void* p) {
    uint32_t a;
    asm("{ .reg .u64 t; cvta.to.shared.u64 t, %1; cvt.u32.u64 %0, t; }" : "=r"(a) : "l"(p));
    return a;
}
__device__ __forceinline__ void cp16(uint32_t sdst, const void* gsrc) {
    asm volatile("cp.async.cg.shared.global [%0], [%1], 16;" :: "r"(sdst), "l"(gsrc) : "memory");
}
__device__ __forceinline__ void ldsm4(uint32_t& r0, uint32_t& r1, uint32_t& r2,
                                      uint32_t& r3, uint32_t a) {
    asm volatile("ldmatrix.sync.aligned.m8n8.x4.shared.b16 {%0,%1,%2,%3}, [%4];"
                 : "=r"(r0), "=r"(r1), "=r"(r2), "=r"(r3) : "r"(a));
}
__device__ __forceinline__ void mma16816h(float* c, uint32_t a0, uint32_t a1,
                                          uint32_t a2, uint32_t a3,
                                          uint32_t b0, uint32_t b1) {
    asm volatile(
        "mma.sync.aligned.m16n8k16.row.col.f32.f16.f16.f32 "
        "{%0,%1,%2,%3}, {%4,%5,%6,%7}, {%8,%9}, {%0,%1,%2,%3};"
        : "+f"(c[0]), "+f"(c[1]), "+f"(c[2]), "+f"(c[3])
        : "r"(a0), "r"(a1), "r"(a2), "r"(a3), "r"(b0), "r"(b1));
}

// W [K,N] fp32 -> Wt [N,K] fp16 (transposed convert)
__global__ void convT_k(const float* __restrict__ W, __half* __restrict__ hi,
                        int K, int N) {
    int idx = blockIdx.x * 256 + threadIdx.x;
    if (idx >= N * K) return;
    int n = idx / K, k = idx - n * K;
    hi[idx] = __float2half_rn(W[(size_t)k * N + n]);
}

// ---------------- HMMA fp16 GEMM via ldmatrix: C = A[M,K] * B[N,K]^T -------------
#define STAGES 3
#define PITCH 80
#define MAT_BYTES (128*PITCH)
#define STAGE_BYTES (2*MAT_BYTES)        // A | B
#define GEMM_SMEM (STAGES*STAGE_BYTES)   // 61440

template <bool OUTHALF>
__global__ void __launch_bounds__(256) gemm_mma(
    const __half* __restrict__ A, const __half* __restrict__ B,
    float* __restrict__ C, __half* __restrict__ Ch, int M, int N, int K) {
    extern __shared__ char sm8[];
    const uint32_t sb = smem_u32(sm8);
    const int tid = threadIdx.x;
    const int lane = tid & 31, wid = tid >> 5;
    const int wm = wid & 3, wn = wid >> 2;
    const int bm = blockIdx.y * 128, bn = blockIdx.x * 128;
    const int g = lane >> 2, tig = lane & 3;
    const int NCH = K >> 5;

    const char* pA = (const char*)A;
    const char* pB = (const char*)B;
    const size_t rowb = (size_t)K * 2;

    auto load_stage = [&](int kc, int s) {
        uint32_t sbase = sb + s * STAGE_BYTES;
        size_t kb = (size_t)kc * 64;
#pragma unroll
        for (int i = tid; i < 512; i += 256) {
            int r = i >> 2, gg = i & 3;
            uint32_t so = sbase + r * PITCH + gg * 16;
            size_t ga = (size_t)(bm + r) * rowb + kb + gg * 16;
            size_t gb = (size_t)(bn + r) * rowb + kb + gg * 16;
            cp16(so,             pA + ga);
            cp16(so + MAT_BYTES, pB + gb);
        }
        asm volatile("cp.async.commit_group;" ::: "memory");
    };

    float acc[2][8][4];
#pragma unroll
    for (int f = 0; f < 2; f++)
#pragma unroll
        for (int nf = 0; nf < 8; nf++)
#pragma unroll
            for (int c = 0; c < 4; c++) acc[f][nf][c] = 0.f;

    const uint32_t rowA = (uint32_t)(wm * 32 + (lane & 7) + ((lane >> 3) & 1) * 8);
    const uint32_t offA = (uint32_t)((lane >> 4) * 16);
    const uint32_t rowB = (uint32_t)(wn * 64 + ((lane >> 4) & 1) * 8 + (lane & 7));
    const uint32_t offB = (uint32_t)(((lane >> 3) & 1) * 16);

    load_stage(0, 0);
    load_stage(1, 1);

    for (int kc = 0; kc < NCH; kc++) {
        int s = kc % STAGES;
        asm volatile("cp.async.wait_group 1;" ::: "memory");
        __syncthreads();
        if (kc + 2 < NCH) load_stage(kc + 2, (kc + 2) % STAGES);
        else asm volatile("cp.async.commit_group;" ::: "memory");

        uint32_t aA = sb + s * STAGE_BYTES;
        uint32_t aB = aA + MAT_BYTES;
#pragma unroll
        for (int kk = 0; kk < 2; kk++) {
            const uint32_t kbase = kk * 32;
            uint32_t ah[2][4];
#pragma unroll
            for (int f = 0; f < 2; f++) {
                uint32_t addr = aA + (rowA + f * 16) * PITCH + kbase + offA;
                ldsm4(ah[f][0], ah[f][1], ah[f][2], ah[f][3], addr);
            }
#pragma unroll
            for (int p = 0; p < 4; p++) {
                uint32_t b0, b1, b2, b3;
                uint32_t addr = aB + (rowB + p * 16) * PITCH + kbase + offB;
                ldsm4(b0, b1, b2, b3, addr);
#pragma unroll
                for (int f = 0; f < 2; f++) {
                    mma16816h(acc[f][2*p],   ah[f][0], ah[f][1], ah[f][2], ah[f][3], b0, b1);
                    mma16816h(acc[f][2*p+1], ah[f][0], ah[f][1], ah[f][2], ah[f][3], b2, b3);
                }
            }
        }
        __syncthreads();
    }

#pragma unroll
    for (int f = 0; f < 2; f++) {
        int r0 = bm + wm * 32 + f * 16 + g;
#pragma unroll
        for (int nf = 0; nf < 8; nf++) {
            int c0 = bn + wn * 64 + nf * 8 + 2 * tig;
            if (OUTHALF) {
                *(__half2*)&Ch[(size_t)r0 * N + c0] =
                    __floats2half2_rn(acc[f][nf][0], acc[f][nf][1]);
                *(__half2*)&Ch[(size_t)(r0 + 8) * N + c0] =
                    __floats2half2_rn(acc[f][nf][2], acc[f][nf][3]);
            } else {
                *(float2*)&C[(size_t)r0 * N + c0]       = make_float2(acc[f][nf][0], acc[f][nf][1]);
                *(float2*)&C[(size_t)(r0 + 8) * N + c0] = make_float2(acc[f][nf][2], acc[f][nf][3]);
            }
        }
    }
}

// ---------------- x @ W1  (K=4) -> fp16, 2 features per thread ----------------
__global__ void lin1_k(const float* __restrict__ x, const float* __restrict__ W,
                       __half* __restrict__ out) {
    int idx = blockIdx.x * 256 + threadIdx.x;
    int n = idx >> 8, f = (idx & 255) * 2;
    float4 xv = *(const float4*)(x + (size_t)n * 4);
    float v0 = xv.x*W[f]   + xv.y*W[512+f]   + xv.z*W[1024+f]   + xv.w*W[1536+f];
    float v1 = xv.x*W[f+1] + xv.y*W[512+f+1] + xv.z*W[1024+f+1] + xv.w*W[1536+f+1];
    *(__half2*)&out[(size_t)n * FDIM + f] = __floats2half2_rn(v0, v1);
}

// ---------------- GAT kernel A: attention (fp16 hpre; atomic-free softmax) -------
template <bool LOOPS>
__global__ void __launch_bounds__(256) gat_attn(
    const __half* __restrict__ hpre,
    const int* __restrict__ esrc, const int* __restrict__ edst,
    const float* __restrict__ ea,
    const float* __restrict__ a_src, const float* __restrict__ a_dst,
    const float* __restrict__ We, const float* __restrict__ ae,
    float* __restrict__ galpha, int* __restrict__ gsrcb, int* __restrict__ goffb) {
    __shared__ float sh_ssrc[400];
    __shared__ float sh_sdst[400];
    __shared__ float sh_alS[EMAX*8];
    __shared__ float sh_den[400];
    __shared__ float sh_av[1024];
    __shared__ float sh_weae[8];
    __shared__ float sh_easum[52];
    __shared__ int   sh_srcS[EMAX];
    __shared__ int   sh_dstS[EMAX];
    __shared__ int   sh_cnt[52];
    __shared__ int   sh_off[52];
    __shared__ int   sh_cur[52];

    const int g = blockIdx.x;
    const int nb = g * NODES;
    const int eb = g * EPG;
    const int tid = threadIdx.x;
    const int lane = tid & 31, wid = tid >> 5;
    const int ECNT = LOOPS ? (EPG + NODES) : EPG;

    if (tid < NODES) { sh_cnt[tid] = 0; sh_easum[tid] = 0.f; sh_cur[tid] = 0; }
    for (int i = tid; i < 512; i += 256) {
        sh_av[i] = a_src[i];
        sh_av[512 + i] = a_dst[i];
    }
    if (tid < 8) {
        float s = 0.f;
#pragma unroll
        for (int c = 0; c < 64; c++) s += We[tid * 64 + c] * ae[tid * 64 + c];
        sh_weae[tid] = s;
    }
    __syncthreads();

    for (int e = tid; e < EPG; e += 256) {
        int d = edst[eb + e] - nb;
        atomicAdd(&sh_cnt[d], 1);
        atomicAdd(&sh_easum[d], ea[eb + e]);
    }
    __syncthreads();

    for (int n = wid; n < NODES; n += 8) {
        const uint2* hr = (const uint2*)(hpre + (size_t)(nb + n) * FDIM);
#pragma unroll
        for (int k = 0; k < 4; k++) {
            uint2 u = hr[lane + 32 * k];
            float2 f01 = __half22float2(*(__half2*)&u.x);
            float2 f23 = __half22float2(*(__half2*)&u.y);
            int f = 4 * lane + 128 * k;
            float4 as = *(const float4*)(sh_av + f);
            float4 ad = *(const float4*)(sh_av + 512 + f);
            float s1 = f01.x*as.x + f01.y*as.y + f23.x*as.z + f23.y*as.w;
            float s2 = f01.x*ad.x + f01.y*ad.y + f23.x*ad.z + f23.y*ad.w;
#pragma unroll
            for (int o = 8; o > 0; o >>= 1) {
                s1 += __shfl_xor_sync(0xffffffffu, s1, o);
                s2 += __shfl_xor_sync(0xffffffffu, s2, o);
            }
            if ((lane & 15) == 0) {
                int head = 2 * k + (lane >> 4);
                sh_ssrc[n * 8 + head] = s1;
                sh_sdst[n * 8 + head] = s2;
            }
        }
    }
    __syncthreads();

    if (tid == 0) {
        int o = 0;
        for (int n = 0; n < NODES; n++) { sh_off[n] = o; o += sh_cnt[n] + (LOOPS ? 1 : 0); }
    }
    __syncthreads();

    for (int e = tid; e < ECNT; e += 256) {
        int sl, dl; float eav;
        if (e < EPG) { sl = esrc[eb + e] - nb; dl = edst[eb + e] - nb; eav = ea[eb + e]; }
        else { sl = dl = e - EPG; eav = sh_easum[dl] / fmaxf((float)sh_cnt[dl], 1.f); }
        int pos = sh_off[dl] + atomicAdd(&sh_cur[dl], 1);
        sh_srcS[pos] = sl; sh_dstS[pos] = dl;
#pragma unroll
        for (int h = 0; h < 8; h++) {
            float al = sh_ssrc[sl * 8 + h] + sh_sdst[dl * 8 + h] + eav * sh_weae[h];
            al = al > 0.f ? al : 0.2f * al;
            sh_alS[pos * 8 + h] = al;
        }
    }
    __syncthreads();

    for (int p = tid; p < NODES * HEADS; p += 256) {
        int n = p >> 3, h = p & 7;
        const int beg = sh_off[n], end = beg + (LOOPS ? (sh_cnt[n] + 1) : sh_cnt[n]);
        float m = 0.f;
        for (int j = beg; j < end; j++) m = fmaxf(m, sh_alS[j * 8 + h]);
        float d = 0.f;
        for (int j = beg; j < end; j++) {
            float pv = __expf(sh_alS[j * 8 + h] - m);
            sh_alS[j * 8 + h] = pv;
            d += pv;
        }
        sh_den[p] = 1.f / (d + 1e-16f);
    }
    __syncthreads();

    float* ga = galpha + (size_t)g * EMAX * 8;
    int* gs = gsrcb + (size_t)g * EMAX;
    for (int i = tid; i < ECNT; i += 256) {
        int dl = sh_dstS[i];
        float4 o0, o1;
        o0.x = sh_alS[i*8+0] * sh_den[dl*8+0];
        o0.y = sh_alS[i*8+1] * sh_den[dl*8+1];
        o0.z = sh_alS[i*8+2] * sh_den[dl*8+2];
        o0.w = sh_alS[i*8+3] * sh_den[dl*8+3];
        o1.x = sh_alS[i*8+4] * sh_den[dl*8+4];
        o1.y = sh_alS[i*8+5] * sh_den[dl*8+5];
        o1.z = sh_alS[i*8+6] * sh_den[dl*8+6];
        o1.w = sh_alS[i*8+7] * sh_den[dl*8+7];
        ((float4*)(ga + i * 8))[0] = o0;
        ((float4*)(ga + i * 8))[1] = o1;
        gs[i] = sh_srcS[i];
    }
    if (tid < NODES) goffb[g * 51 + tid] = sh_off[tid];
    if (tid == NODES) goffb[g * 51 + NODES] = ECNT;
}

// ---------------- GAT kernel B: aggregation (fp16 hpre; x4-vectorized) -----------
template <bool OUTFP16>
__global__ void __launch_bounds__(256) gat_aggr(
    const __half* __restrict__ hpre,
    const float* __restrict__ galpha, const int* __restrict__ gsrcb,
    const int* __restrict__ goffb,
    const float* __restrict__ bias, float* __restrict__ xout,
    __half* __restrict__ outh) {
    __shared__ float sh_hs[NODES * 128];
    __shared__ float sh_al[EMAX * 2];
    __shared__ int   sh_src[EMAX];
    __shared__ int   sh_off[51];

    const int sl = blockIdx.x;
    const int g = blockIdx.y;
    const int nb = g * NODES;
    const int tid = threadIdx.x;
    const int lane = tid & 31, wg = tid >> 5;
    const int ECNT = goffb[g * 51 + NODES];

    for (int i = tid; i < NODES * 64; i += 256) {
        int n = i >> 6, ff2 = i & 63;
        __half2 v = *(const __half2*)(hpre + (size_t)(nb + n) * FDIM + sl * 128 + ff2 * 2);
        float2 f = __half22float2(v);
        sh_hs[n * 128 + ff2 * 2]     = f.x;
        sh_hs[n * 128 + ff2 * 2 + 1] = f.y;
    }
    const float* ga = galpha + (size_t)g * EMAX * 8 + sl * 2;
    const int* gs = gsrcb + (size_t)g * EMAX;
    for (int i = tid; i < ECNT; i += 256) {
        sh_al[i * 2]     = ga[i * 8];
        sh_al[i * 2 + 1] = ga[i * 8 + 1];
        sh_src[i] = gs[i];
    }
    if (tid <= NODES) sh_off[tid] = goffb[g * 51 + tid];
    __syncthreads();

    const int hsel = lane >> 4;
    const int f0 = lane * 4;
    const float4 bv = *(const float4*)(bias + sl * 128 + f0);
    for (int n = wg; n < NODES; n += 8) {
        float4 acc = {0.f, 0.f, 0.f, 0.f};
        const int beg = sh_off[n], end = sh_off[n + 1];
        for (int j = beg; j < end; j++) {
            const int s = sh_src[j];
            const float a = sh_al[j * 2 + hsel];
            const float4 h = *(const float4*)(sh_hs + s * 128 + f0);
            acc.x += a * h.x; acc.y += a * h.y;
            acc.z += a * h.z; acc.w += a * h.w;
        }
        float4 v;
        v.x = fmaxf(acc.x + bv.x, 0.f);
        v.y = fmaxf(acc.y + bv.y, 0.f);
        v.z = fmaxf(acc.z + bv.z, 0.f);
        v.w = fmaxf(acc.w + bv.w, 0.f);
        size_t idx = (size_t)(nb + n) * FDIM + sl * 128 + f0;
        if (OUTFP16) {
            __half2* op = (__half2*)(outh + idx);
            op[0] = __floats2half2_rn(v.x, v.y);
            op[1] = __floats2half2_rn(v.z, v.w);
        } else {
            *(float4*)(xout + idx) = v;
        }
    }
}

// ---------------- fused pool + agent rows -> fp16 GRU GEMM operand ---------------
__global__ void poolagent_k(const float* __restrict__ x3, __half* __restrict__ Ah) {
    int b = blockIdx.x;
    int f = blockIdx.y * 128 + threadIdx.x;
    float s = 0.f;
#pragma unroll 10
    for (int n = 0; n < NODES; n++) {
        float v = x3[(size_t)(b * NODES + n) * FDIM + f];
        s += v;
        if (n < NA)
            Ah[(size_t)(b * NA + n) * GRUI + f] = __float2half_rn(v);
    }
    __half h = __float2half_rn(s * (1.f / 50.f));
#pragma unroll
    for (int t = 0; t < NA; t++)
        Ah[(size_t)(b * NA + t) * GRUI + 512 + f] = h;
}

// ---------------- full GRU (5 steps in one kernel); 8 graphs per CTA -------------
__global__ void __launch_bounds__(256) gru_all(
    const float* __restrict__ GI, const float* __restrict__ h0,
    const float* __restrict__ Whh, const float* __restrict__ bih,
    const float* __restrict__ bhh, float* __restrict__ gout,
    float* __restrict__ hlast) {
    __shared__ float sh_h[8 * GRUH];
    __shared__ float sh_gh[8 * G3];
    const int b0 = blockIdx.x * 8;
    const int tid = threadIdx.x;
    for (int i = tid; i < 8 * GRUH; i += 256) sh_h[i] = h0[b0 * GRUH + i];
    __syncthreads();
    for (int t = 0; t < NA; t++) {
#pragma unroll
        for (int v = 0; v < 12; v++) {
            int idx = v * 256 + tid;
            int gg = idx / G3, j = idx - gg * G3;
            const float* hr = sh_h + gg * GRUH;
            float acc = 0.f;
#pragma unroll 8
            for (int k = 0; k < GRUH; k++) acc += hr[k] * Whh[k * G3 + j];
            sh_gh[idx] = acc;
        }
        __syncthreads();
#pragma unroll
        for (int v = 0; v < 4; v++) {
            int idx = v * 256 + tid;
            int gg = idx >> 7, j = idx & 127;
            int bg = b0 + gg;
            const float* gi = GI + (size_t)(bg * NA + t) * G3;
            const float* gh = sh_gh + gg * G3;
            float ir = gi[j] + bih[j];
            float iz = gi[j + 128] + bih[j + 128];
            float inn = gi[j + 256] + bih[j + 256];
            float hr_ = gh[j] + bhh[j];
            float hz = gh[j + 128] + bhh[j + 128];
            float hn = gh[j + 256] + bhh[j + 256];
            float r = 1.f / (1.f + expf(-(ir + hr_)));
            float z = 1.f / (1.f + expf(-(iz + hz)));
            float nn = tanhf(inn + r * hn);
            float h = (1.f - z) * nn + z * sh_h[idx];
            sh_h[idx] = h;
            gout[(size_t)(bg * NA + t) * GRUH + j] = h;
        }
        __syncthreads();
    }
    for (int i = tid; i < 8 * GRUH; i += 256) hlast[b0 * GRUH + i] = sh_h[i];
}

// ---------------- FC head ----------------
__global__ void fc_k(const float* __restrict__ gout, const float* __restrict__ W1,
                     const float* __restrict__ b1, const float* __restrict__ W2,
                     const float* __restrict__ b2, const float* __restrict__ ls,
                     float* __restrict__ out) {
    __shared__ float g[128];
    __shared__ float f1[64];
    int r = blockIdx.x, tid = threadIdx.x;
    g[tid] = gout[(size_t)r * GRUH + tid];
    g[tid + 64] = gout[(size_t)r * GRUH + tid + 64];
    __syncthreads();
    float acc = b1[tid];
#pragma unroll 8
    for (int k = 0; k < 128; k++) acc += g[k] * W1[k * 64 + tid];
    f1[tid] = acc > 0.f ? acc : 0.f;
    __syncthreads();
    if (tid < 3) {
        float a2 = b2[tid];
#pragma unroll
        for (int k = 0; k < 64; k++) a2 += f1[k] * W2[k * 3 + tid];
        out[r * 3 + tid] = a2;
        float l = ls[tid];
        l = fminf(fmaxf(l, -20.f), 2.f);
        out[NGRAPH * NA * 3 + r * 3 + tid] = expf(l);
    }
}

// ---------------- launch ----------------
extern "C" void kernel_launch(void* const* d_in, const int* in_sizes, int n_in,
                              void* d_out, int out_size) {
    const float* x      = (const float*)d_in[0];
    const int*   ei     = (const int*)d_in[1];
    const float* ea     = (const float*)d_in[2];
    const float* hid0   = (const float*)d_in[3];
    const float* W1     = (const float*)d_in[4];
    const float* a_s1   = (const float*)d_in[5];
    const float* a_d1   = (const float*)d_in[6];
    const float* We1    = (const float*)d_in[7];
    const float* ae1    = (const float*)d_in[8];
    const float* b1     = (const float*)d_in[9];
    const float* W2     = (const float*)d_in[10];
    const float* a_s2   = (const float*)d_in[11];
    const float* a_d2   = (const float*)d_in[12];
    const float* We2    = (const float*)d_in[13];
    const float* ae2    = (const float*)d_in[14];
    const float* b2     = (const float*)d_in[15];
    const float* W3     = (const float*)d_in[16];
    const float* a_s3   = (const float*)d_in[17];
    const float* a_d3   = (const float*)d_in[18];
    const float* We3    = (const float*)d_in[19];
    const float* ae3    = (const float*)d_in[20];
    const float* b3     = (const float*)d_in[21];
    const float* Wih    = (const float*)d_in[22];
    const float* Whh    = (const float*)d_in[23];
    const float* bih    = (const float*)d_in[24];
    const float* bhh    = (const float*)d_in[25];
    const float* fc1W   = (const float*)d_in[26];
    const float* fc1b   = (const float*)d_in[27];
    const float* fc2W   = (const float*)d_in[28];
    const float* fc2b   = (const float*)d_in[29];
    const float* logstd = (const float*)d_in[30];
    float* out = (float*)d_out;

    float *bufB, *GI, *gout, *alphab;
    int *srcb, *offb;
    __half *Hh, *Ah, *Bh;
    cudaGetSymbolAddress((void**)&Hh,   g_Hh);
    cudaGetSymbolAddress((void**)&bufB, g_bufB);
    cudaGetSymbolAddress((void**)&GI,   g_GI);
    cudaGetSymbolAddress((void**)&gout, g_gruout);
    cudaGetSymbolAddress((void**)&alphab, g_alpha);
    cudaGetSymbolAddress((void**)&srcb, g_srcb);
    cudaGetSymbolAddress((void**)&offb, g_offb);
    cudaGetSymbolAddress((void**)&Ah, g_Ah);
    cudaGetSymbolAddress((void**)&Bh, g_Bh);

    cudaFuncSetAttribute((const void*)gemm_mma<false>,
                         cudaFuncAttributeMaxDynamicSharedMemorySize, GEMM_SMEM);
    cudaFuncSetAttribute((const void*)gemm_mma<true>,
                         cudaFuncAttributeMaxDynamicSharedMemorySize, GEMM_SMEM);

    const int* esrc = ei;
    const int* edst = ei + NE;

    // layer 1
    lin1_k<<<NN, 256>>>(x, W1, Hh);
    gat_attn<false><<<NGRAPH, 256>>>(Hh, esrc, edst, ea, a_s1, a_d1, We1, ae1,
                                     alphab, srcb, offb);
    gat_aggr<true><<<dim3(4, NGRAPH), 256>>>(Hh, alphab, srcb, offb, b1,
                                             nullptr, Ah);
    // layer 2
    convT_k<<<(FDIM * FDIM + 255) / 256, 256>>>(W2, Bh, FDIM, FDIM);
    gemm_mma<true><<<dim3(FDIM / 128, NN / 128), 256, GEMM_SMEM>>>(
        Ah, Bh, nullptr, Hh, NN, FDIM, FDIM);
    gat_attn<true><<<NGRAPH, 256>>>(Hh, esrc, edst, ea, a_s2, a_d2, We2, ae2,
                                    alphab, srcb, offb);
    gat_aggr<true><<<dim3(4, NGRAPH), 256>>>(Hh, alphab, srcb, offb, b2,
                                             nullptr, Ah);
    // layer 3
    convT_k<<<(FDIM * FDIM + 255) / 256, 256>>>(W3, Bh, FDIM, FDIM);
    gemm_mma<true><<<dim3(FDIM / 128, NN / 128), 256, GEMM_SMEM>>>(
        Ah, Bh, nullptr, Hh, NN, FDIM, FDIM);
    gat_attn<true><<<NGRAPH, 256>>>(Hh, esrc, edst, ea, a_s3, a_d3, We3, ae3,
                                    alphab, srcb, offb);
    gat_aggr<false><<<dim3(4, NGRAPH), 256>>>(Hh, alphab, srcb, offb, b3,
                                              bufB, nullptr);
    // fused pool + agent -> fp16 GRU GEMM operand, then GI GEMM
    poolagent_k<<<dim3(NGRAPH, FDIM / 128), 128>>>(bufB, Ah);
    convT_k<<<(GRUI * G3 + 255) / 256, 256>>>(Wih, Bh, GRUI, G3);
    gemm_mma<false><<<dim3(G3 / 128, (NGRAPH * NA) / 128), 256, GEMM_SMEM>>>(
        Ah, Bh, GI, nullptr, NGRAPH * NA, G3, GRUI);
    // GRU: single kernel, reads hid0 directly, writes h_last straight into out
    gru_all<<<NGRAPH / 8, 256>>>(GI, hid0, Whh, bih, bhh, gout,
                                 out + NGRAPH * NA * 3 * 2);
    // FC head
    fc_k<<<NGRAPH * NA, 64>>>(gout, fc1W, fc1b, fc2W, fc2b, logstd, out);
}